// round 10
// baseline (speedup 1.0000x reference)
#include <cuda_runtime.h>

#define NH 1024
#define NB 64
#define TT 512
#define THH 256

// output layout (floats): hys[B,T,H] | hzs[B,T,H] | us[B,256,H] | spikes[B,256,H]
#define HZS_OFF 33554432ull
#define US_OFF  67108864ull
#define SP_OFF  83886080ull

// ---------------- device scratch (static globals: allocation-free) ---------
__device__ float g_hy[2][NH][NB];              // ping-pong hy state, transposed [k][b]
__device__ float g_hz[NH][NB];                 // hz state, transposed
__device__ float g_xw[(size_t)THH * NB * NH];  // x_t @ x2h, [t][b][n]  (64 MB)
__device__ float g_hyW[NB * NH];               // hy_final @ h2h, [b][n]

// --------------------------------- init ------------------------------------
__global__ void init_kernel() {
    int i = blockIdx.x * blockDim.x + threadIdx.x;
    if (i < NH * NB) {
        ((float*)g_hy)[i] = 0.0f;   // zero buffer 0 only (step 0 reads it)
        ((float*)g_hz)[i] = 0.0f;
    }
}

// --------------- xw[t][b][n] = sum_i x[b][t][i] * x2h[i][n] ----------------
// grid (8, 256): x = n-block of 128, y = t.  256 threads.
__global__ void xw_kernel(const float* __restrict__ x,
                          const float* __restrict__ x2h) {
    __shared__ float xS[64][64];
    const int t = blockIdx.y, n0 = blockIdx.x * 128, tid = threadIdx.x;
    {
        int b = tid >> 2, part = tid & 3;
        const float4* src = (const float4*)(x + ((size_t)b * TT + t) * 64 + part * 16);
        float4* dst = (float4*)&xS[b][part * 16];
        dst[0] = src[0]; dst[1] = src[1]; dst[2] = src[2]; dst[3] = src[3];
    }
    __syncthreads();
    const int n = n0 + (tid & 127);
    const int b0 = (tid >> 7) * 32;
    float acc[32];
#pragma unroll
    for (int bb = 0; bb < 32; ++bb) acc[bb] = 0.0f;
    for (int i = 0; i < 64; ++i) {
        float w = __ldg(&x2h[(size_t)i * NH + n]);
#pragma unroll
        for (int bb = 0; bb < 32; ++bb) acc[bb] = fmaf(xS[b0 + bb][i], w, acc[bb]);
    }
#pragma unroll
    for (int bb = 0; bb < 32; ++bb)
        g_xw[((size_t)t * NB + b0 + bb) * NH + n] = acc[bb];
}

// --------------------------- one harmonic step -----------------------------
// 128 CTAs; CTA c owns hidden cols [8c, 8c+8).  256 threads: b = tid&63,
// K-split kp = tid>>6 (256 k each).  GEMM -> smem reduce -> fused update.
__global__ void __launch_bounds__(256) step_kernel(
    const float* __restrict__ W, const float* __restrict__ bias,
    const float* __restrict__ gam, const float* __restrict__ eps,
    float* __restrict__ out, int s) {
    __shared__ float Wb[NH][8];      // 32 KB weight slice
    __shared__ float P[4][8][64];    // K-partials
    __shared__ float SH[8][64], SZ[8][64];

    const int tid = threadIdx.x, n0 = blockIdx.x * 8;
    for (int k = tid; k < NH; k += 256) {
        float4 a = *(const float4*)(W + (size_t)k * NH + n0);
        float4 c = *(const float4*)(W + (size_t)k * NH + n0 + 4);
        *(float4*)&Wb[k][0] = a;
        *(float4*)&Wb[k][4] = c;
    }
    __syncthreads();

    const int b = tid & 63, kp = tid >> 6, cur = s & 1;
    const float* hyp = &g_hy[cur][0][0];
    float acc[8];
#pragma unroll
    for (int j = 0; j < 8; ++j) acc[j] = 0.0f;
    const int k0 = kp * 256;
#pragma unroll 4
    for (int k = k0; k < k0 + 256; ++k) {
        float h = __ldg(hyp + (size_t)k * NB + b);
        float4 wA = *(const float4*)&Wb[k][0];
        float4 wB = *(const float4*)&Wb[k][4];
        acc[0] = fmaf(h, wA.x, acc[0]); acc[1] = fmaf(h, wA.y, acc[1]);
        acc[2] = fmaf(h, wA.z, acc[2]); acc[3] = fmaf(h, wA.w, acc[3]);
        acc[4] = fmaf(h, wB.x, acc[4]); acc[5] = fmaf(h, wB.y, acc[5]);
        acc[6] = fmaf(h, wB.z, acc[6]); acc[7] = fmaf(h, wB.w, acc[7]);
    }
#pragma unroll
    for (int j = 0; j < 8; ++j) P[kp][j][b] = acc[j];
    __syncthreads();

    {
        const int j = tid >> 6;
#pragma unroll
        for (int q = 0; q < 2; ++q) {
            const int jj = j + 4 * q, n = n0 + jj;
            float sum = P[0][jj][b] + P[1][jj][b] + P[2][jj][b] + P[3][jj][b];
            float hy = g_hy[cur][n][b], hz = g_hz[n][b];
            float sv = sum + g_xw[((size_t)s * NB + b) * NH + n] + bias[n];
            float nhz = hz + 0.042f * (tanhf(sv) - gam[n] * hy - eps[n] * hz);
            float nhy = hy + 0.042f * nhz;
            g_hy[cur ^ 1][n][b] = nhy;
            g_hz[n][b] = nhz;
            SH[jj][b] = nhy;
            SZ[jj][b] = nhz;
        }
    }
    __syncthreads();

    if (tid < 64) {  // coalesced 32B trajectory stores
        size_t o = ((size_t)tid * TT + s) * NH + n0;
        float4* h1 = (float4*)(out + o);
        h1[0] = make_float4(SH[0][tid], SH[1][tid], SH[2][tid], SH[3][tid]);
        h1[1] = make_float4(SH[4][tid], SH[5][tid], SH[6][tid], SH[7][tid]);
        float4* h2 = (float4*)(out + HZS_OFF + o);
        h2[0] = make_float4(SZ[0][tid], SZ[1][tid], SZ[2][tid], SZ[3][tid]);
        h2[1] = make_float4(SZ[4][tid], SZ[5][tid], SZ[6][tid], SZ[7][tid]);
    }
}

// ----------------------- hyW = hy_final @ h2h ------------------------------
__global__ void __launch_bounds__(256) hyw_kernel(const float* __restrict__ W) {
    __shared__ float Wb[NH][8];
    __shared__ float P[4][8][64];
    const int tid = threadIdx.x, n0 = blockIdx.x * 8;
    for (int k = tid; k < NH; k += 256) {
        float4 a = *(const float4*)(W + (size_t)k * NH + n0);
        float4 c = *(const float4*)(W + (size_t)k * NH + n0 + 4);
        *(float4*)&Wb[k][0] = a;
        *(float4*)&Wb[k][4] = c;
    }
    __syncthreads();
    const int b = tid & 63, kp = tid >> 6;
    const float* hyp = &g_hy[0][0][0];  // final hy lives in buffer 0 (256 steps)
    float acc[8];
#pragma unroll
    for (int j = 0; j < 8; ++j) acc[j] = 0.0f;
    const int k0 = kp * 256;
#pragma unroll 4
    for (int k = k0; k < k0 + 256; ++k) {
        float h = __ldg(hyp + (size_t)k * NB + b);
        float4 wA = *(const float4*)&Wb[k][0];
        float4 wB = *(const float4*)&Wb[k][4];
        acc[0] = fmaf(h, wA.x, acc[0]); acc[1] = fmaf(h, wA.y, acc[1]);
        acc[2] = fmaf(h, wA.z, acc[2]); acc[3] = fmaf(h, wA.w, acc[3]);
        acc[4] = fmaf(h, wB.x, acc[4]); acc[5] = fmaf(h, wB.y, acc[5]);
        acc[6] = fmaf(h, wB.z, acc[6]); acc[7] = fmaf(h, wB.w, acc[7]);
    }
#pragma unroll
    for (int j = 0; j < 8; ++j) P[kp][j][b] = acc[j];
    __syncthreads();
    const int j = tid >> 6;
#pragma unroll
    for (int q = 0; q < 2; ++q) {
        const int jj = j + 4 * q;
        g_hyW[(size_t)b * NH + n0 + jj] =
            P[0][jj][b] + P[1][jj][b] + P[2][jj][b] + P[3][jj][b];
    }
}

// ------------------------- spiking (LIF) phase -----------------------------
__global__ void spike_kernel(float* __restrict__ out) {
    const int idx = blockIdx.x * 256 + threadIdx.x;   // 65536 threads
    const int b = idx >> 10, n = idx & 1023;
    const float hw = g_hyW[idx];
    float* us = out + US_OFF;
    float* sp = out + SP_OFF;
    float u = 0.0f;
    for (int t = 0; t < THH; ++t) {
        float spike = (u > 0.008f) ? 1.0f : 0.0f;
        if (u > 0.008f) u = 0.001f;
        u = u + (-u + hw + g_xw[((size_t)t * NB + b) * NH + n]) * 0.00105f;
        const size_t o = ((size_t)b * THH + t) * NH + n;
        us[o] = u;
        sp[o] = spike;
    }
}

// ----------- broadcast hy/hz into trajectory for t in [256, 512) -----------
__global__ void fill_kernel(float* __restrict__ out) {
    const int idx = blockIdx.x * 256 + threadIdx.x;   // 65536 threads
    const int b = idx >> 10, n = idx & 1023;
    const float hy = g_hy[0][n][b], hz = g_hz[n][b];
    float* hys = out;
    float* hzs = out + HZS_OFF;
    for (int t = THH; t < TT; ++t) {
        const size_t o = ((size_t)b * TT + t) * NH + n;
        hys[o] = hy;
        hzs[o] = hz;
    }
}

// ---------------------------------------------------------------------------
extern "C" void kernel_launch(void* const* d_in, const int* in_sizes, int n_in,
                              void* d_out, int out_size) {
    const float* x    = (const float*)d_in[0];
    const float* x2h  = (const float*)d_in[1];
    const float* h2h  = (const float*)d_in[2];
    const float* bias = (const float*)d_in[3];
    const float* gam  = (const float*)d_in[4];
    const float* eps  = (const float*)d_in[5];
    float* out = (float*)d_out;

    init_kernel<<<256, 256>>>();
    xw_kernel<<<dim3(8, 256), 256>>>(x, x2h);
    for (int s = 0; s < THH; ++s)
        step_kernel<<<128, 256>>>(h2h, bias, gam, eps, out, s);
    hyw_kernel<<<128, 256>>>(h2h);
    spike_kernel<<<256, 256>>>(out);
    fill_kernel<<<256, 256>>>(out);
}

// round 11
// speedup vs baseline: 2.4286x; 2.4286x over previous
#include <cuda_runtime.h>

#define NH 1024
#define NB 64
#define TT 512
#define THH 256
#define NCTA 128

// output layout (floats): hys[B,T,H] | hzs[B,T,H] | us[B,256,H] | spikes[B,256,H]
#define HZS_OFF 33554432ull
#define US_OFF  67108864ull
#define SP_OFF  83886080ull

typedef unsigned long long ull;

// ---------------- device scratch (static globals: allocation-free) ---------
__device__ float g_hy[2][NH][NB];              // ping-pong hy, transposed [k][b]
__device__ float g_hz[NH][NB];                 // final hz, transposed
__device__ float g_xw[(size_t)THH * NB * NH];  // x_t @ x2h, [t][b][n]
__device__ float g_hyW[NB * NH];               // hy_final @ h2h, [b][n]
__device__ unsigned g_bar;

__device__ __forceinline__ ull fma2(ull a, ull b, ull c) {
    ull d; asm("fma.rn.f32x2 %0, %1, %2, %3;" : "=l"(d) : "l"(a), "l"(b), "l"(c));
    return d;
}
__device__ __forceinline__ ull pack2(float x) {
    ull r; asm("mov.b64 %0, {%1, %1};" : "=l"(r) : "f"(x)); return r;
}
__device__ __forceinline__ void unpack2(ull v, float& lo, float& hi) {
    asm("mov.b64 {%0, %1}, %2;" : "=f"(lo), "=f"(hi) : "l"(v));
}

// --------------------------------- init ------------------------------------
__global__ void init_kernel() {
    int i = blockIdx.x * blockDim.x + threadIdx.x;
    if (i < NH * NB) ((float*)g_hy)[i] = 0.0f;  // buffer 0 only (step 0 reads it)
    if (i == 0) g_bar = 0u;
}

// --------------- xw[t][b][n] = sum_i x[b][t][i] * x2h[i][n] ----------------
__global__ void xw_kernel(const float* __restrict__ x,
                          const float* __restrict__ x2h) {
    __shared__ float xS[64][64];
    const int t = blockIdx.y, n0 = blockIdx.x * 128, tid = threadIdx.x;
    {
        int b = tid >> 2, part = tid & 3;
        const float4* src = (const float4*)(x + ((size_t)b * TT + t) * 64 + part * 16);
        float4* dst = (float4*)&xS[b][part * 16];
        dst[0] = src[0]; dst[1] = src[1]; dst[2] = src[2]; dst[3] = src[3];
    }
    __syncthreads();
    const int n = n0 + (tid & 127);
    const int b0 = (tid >> 7) * 32;
    float acc[32];
#pragma unroll
    for (int bb = 0; bb < 32; ++bb) acc[bb] = 0.0f;
    for (int i = 0; i < 64; ++i) {
        float w = __ldg(&x2h[(size_t)i * NH + n]);
#pragma unroll
        for (int bb = 0; bb < 32; ++bb) acc[bb] = fmaf(xS[b0 + bb][i], w, acc[bb]);
    }
#pragma unroll
    for (int bb = 0; bb < 32; ++bb)
        g_xw[((size_t)t * NB + b0 + bb) * NH + n] = acc[bb];
}

// ----------------- persistent harmonic kernel (256 steps + hyW) ------------
// 128 CTAs = 64 col-blocks x 2 batch-halves. CTA owns 16 cols x 32 batches.
// GEMM role:   lane b = b0+(tid&31), K-split kp = tid>>5 (128 k each).
// Update role: j = tid&15, ub = tid>>4 -> states (j,ub) and (j,ub+16),
//              hy/hz live in registers for the whole run.
__global__ void __launch_bounds__(256, 1) harm_kernel(
    const float* __restrict__ W, const float* __restrict__ bias,
    const float* __restrict__ gam, const float* __restrict__ eps,
    float* __restrict__ out) {
    extern __shared__ float sm[];
    float* Wb = sm;                  // [1024][16]   64 KB
    float* P  = sm + NH * 16;        // [8][16][33]  16.9 KB

    const int tid = threadIdx.x;
    const int n0 = (blockIdx.x >> 1) * 16, b0 = (blockIdx.x & 1) * 32;

    // load W slice ONCE for the whole run
    for (int k = tid; k < NH; k += 256) {
        const float4* src = (const float4*)(W + (size_t)k * NH + n0);
        float4* dst = (float4*)(Wb + k * 16);
        dst[0] = src[0]; dst[1] = src[1]; dst[2] = src[2]; dst[3] = src[3];
    }

    const int uj = tid & 15, ub = tid >> 4;
    const int n_u = n0 + uj;
    const float bi = bias[n_u], ga = gam[n_u], ep = eps[n_u];
    float hyA = 0.0f, hzA = 0.0f, hyB = 0.0f, hzB = 0.0f;

    const int bg = b0 + (tid & 31), kp = tid >> 5, k0 = kp * 128;
    const int bl = tid & 31;
    __syncthreads();

    for (int s = 0; s <= THH; ++s) {
        const int cur = s & 1;
        const float* hyp = &g_hy[cur][0][0];

        // prefetch xw for update phase (latency hidden under GEMM)
        float xwA = 0.0f, xwB = 0.0f;
        if (s < THH) {
            xwA = __ldg(&g_xw[((size_t)s * NB + b0 + ub) * NH + n_u]);
            xwB = __ldg(&g_xw[((size_t)s * NB + b0 + ub + 16) * NH + n_u]);
        }

        // ---- GEMM: acc over this thread's 128-k slice, 16 cols as 8 f32x2 ----
        ull acc[8];
#pragma unroll
        for (int p = 0; p < 8; ++p) acc[p] = 0ull;
        float hb[8];
#pragma unroll
        for (int q = 0; q < 8; ++q) hb[q] = __ldcg(hyp + (size_t)(k0 + q) * NB + bg);
        for (int kb = 0; kb < 128; kb += 8) {
            float hc[8];
#pragma unroll
            for (int q = 0; q < 8; ++q) hc[q] = hb[q];
            if (kb + 8 < 128) {
#pragma unroll
                for (int q = 0; q < 8; ++q)
                    hb[q] = __ldcg(hyp + (size_t)(k0 + kb + 8 + q) * NB + bg);
            }
#pragma unroll
            for (int q = 0; q < 8; ++q) {
                ull hh = pack2(hc[q]);
                const ulonglong2* wp = (const ulonglong2*)(Wb + (k0 + kb + q) * 16);
                ulonglong2 A = wp[0], B2 = wp[1], C = wp[2], D = wp[3];
                acc[0] = fma2(hh, A.x, acc[0]);  acc[1] = fma2(hh, A.y, acc[1]);
                acc[2] = fma2(hh, B2.x, acc[2]); acc[3] = fma2(hh, B2.y, acc[3]);
                acc[4] = fma2(hh, C.x, acc[4]);  acc[5] = fma2(hh, C.y, acc[5]);
                acc[6] = fma2(hh, D.x, acc[6]);  acc[7] = fma2(hh, D.y, acc[7]);
            }
        }
        // partials -> SMEM (lanes vary b: conflict-free)
        {
            float* pr = P + (size_t)kp * 16 * 33;
#pragma unroll
            for (int p = 0; p < 8; ++p) {
                float lo, hi; unpack2(acc[p], lo, hi);
                pr[(2 * p) * 33 + bl] = lo;
                pr[(2 * p + 1) * 33 + bl] = hi;
            }
        }
        __syncthreads();

        // ---- reduce over 8 K-splits + fused update (2 states/thread) ----
        float sA = 0.0f, sB = 0.0f;
#pragma unroll
        for (int q = 0; q < 8; ++q) {
            const float* pr = P + ((size_t)q * 16 + uj) * 33;
            sA += pr[ub];
            sB += pr[ub + 16];
        }
        if (s < THH) {
            float tA = tanhf(sA + xwA + bi);
            hzA = hzA + 0.042f * (tA - ga * hyA - ep * hzA);
            hyA = hyA + 0.042f * hzA;
            float tB = tanhf(sB + xwB + bi);
            hzB = hzB + 0.042f * (tB - ga * hyB - ep * hzB);
            hyB = hyB + 0.042f * hzB;

            g_hy[cur ^ 1][n_u][b0 + ub]      = hyA;
            g_hy[cur ^ 1][n_u][b0 + ub + 16] = hyB;

            size_t oA = ((size_t)(b0 + ub) * TT + s) * NH + n_u;
            size_t oB = ((size_t)(b0 + ub + 16) * TT + s) * NH + n_u;
            out[oA] = hyA;             out[oB] = hyB;
            out[HZS_OFF + oA] = hzA;   out[HZS_OFF + oB] = hzB;
            if (s == THH - 1) {
                g_hz[n_u][b0 + ub]      = hzA;
                g_hz[n_u][b0 + ub + 16] = hzB;
            }
            // ---- grid barrier ----
            __threadfence();
            __syncthreads();
            if (tid == 0) {
                unsigned tgt = (unsigned)NCTA * (unsigned)(s + 1);
                atomicAdd(&g_bar, 1u);
                while (*(volatile unsigned*)&g_bar < tgt) { }
            }
            __syncthreads();
        } else {
            // s == 256: hyW = hy_final @ h2h
            g_hyW[(size_t)(b0 + ub) * NH + n_u]      = sA;
            g_hyW[(size_t)(b0 + ub + 16) * NH + n_u] = sB;
        }
    }
}

// ------------------------- spiking (LIF) phase -----------------------------
__global__ void spike_kernel(float* __restrict__ out) {
    const int idx = blockIdx.x * 256 + threadIdx.x;   // 65536 threads
    const int b = idx >> 10, n = idx & 1023;
    const float hw = g_hyW[idx];
    float* us = out + US_OFF;
    float* sp = out + SP_OFF;
    float u = 0.0f;
    for (int t = 0; t < THH; ++t) {
        float spike = (u > 0.008f) ? 1.0f : 0.0f;
        if (u > 0.008f) u = 0.001f;
        u = u + (-u + hw + g_xw[((size_t)t * NB + b) * NH + n]) * 0.00105f;
        const size_t o = ((size_t)b * THH + t) * NH + n;
        us[o] = u;
        sp[o] = spike;
    }
}

// ----------- broadcast hy/hz into trajectory for t in [256, 512) -----------
__global__ void fill_kernel(float* __restrict__ out) {
    const int idx = blockIdx.x * 256 + threadIdx.x;   // 65536 threads
    const int b = idx >> 10, n = idx & 1023;
    const float hy = g_hy[0][n][b], hz = g_hz[n][b];
    float* hys = out;
    float* hzs = out + HZS_OFF;
    for (int t = THH; t < TT; ++t) {
        const size_t o = ((size_t)b * TT + t) * NH + n;
        hys[o] = hy;
        hzs[o] = hz;
    }
}

// ---------------------------------------------------------------------------
extern "C" void kernel_launch(void* const* d_in, const int* in_sizes, int n_in,
                              void* d_out, int out_size) {
    const float* x    = (const float*)d_in[0];
    const float* x2h  = (const float*)d_in[1];
    const float* h2h  = (const float*)d_in[2];
    const float* bias = (const float*)d_in[3];
    const float* gam  = (const float*)d_in[4];
    const float* eps  = (const float*)d_in[5];
    float* out = (float*)d_out;

    const int smem = NH * 16 * 4 + 8 * 16 * 33 * 4;   // 82432 B
    static int attr_done = 0;
    if (!attr_done) {
        cudaFuncSetAttribute(harm_kernel,
                             cudaFuncAttributeMaxDynamicSharedMemorySize, smem);
        attr_done = 1;
    }

    init_kernel<<<256, 256>>>();
    xw_kernel<<<dim3(8, 256), 256>>>(x, x2h);
    harm_kernel<<<NCTA, 256, smem>>>(h2h, bias, gam, eps, out);
    spike_kernel<<<256, 256>>>(out);
    fill_kernel<<<256, 256>>>(out);
}

// round 12
// speedup vs baseline: 2.4936x; 1.0268x over previous
#include <cuda_runtime.h>

#define NH 1024
#define NB 64
#define TT 512
#define THH 256
#define NCTA 128

// output layout (floats): hys[B,T,H] | hzs[B,T,H] | us[B,256,H] | spikes[B,256,H]
#define HZS_OFF 33554432ull
#define US_OFF  67108864ull
#define SP_OFF  83886080ull

typedef unsigned long long ull;

// ---------------- device scratch (static globals: allocation-free) ---------
__device__ float g_hy[2][NH][NB];              // ping-pong hy, transposed [k][b]
__device__ float g_hz[NH][NB];                 // final hz, transposed
__device__ float g_xw[(size_t)THH * NB * NH];  // x_t @ x2h, [t][b][n]
__device__ float g_hyW[NB * NH];               // hy_final @ h2h, [b][n]
__device__ unsigned g_bar2[64];                // [0] and [32]: per-half counters

__device__ __forceinline__ ull fma2(ull a, ull b, ull c) {
    ull d; asm("fma.rn.f32x2 %0, %1, %2, %3;" : "=l"(d) : "l"(a), "l"(b), "l"(c));
    return d;
}
__device__ __forceinline__ ull pack2(float x) {
    ull r; asm("mov.b64 %0, {%1, %1};" : "=l"(r) : "f"(x)); return r;
}
__device__ __forceinline__ void unpack2(ull v, float& lo, float& hi) {
    asm("mov.b64 {%0, %1}, %2;" : "=f"(lo), "=f"(hi) : "l"(v));
}
__device__ __forceinline__ void bar_arrive(unsigned* p) {
    asm volatile("red.release.gpu.global.add.u32 [%0], 1;" :: "l"(p) : "memory");
}
__device__ __forceinline__ unsigned bar_peek(unsigned* p) {
    unsigned v;
    asm volatile("ld.acquire.gpu.global.u32 %0, [%1];" : "=r"(v) : "l"(p) : "memory");
    return v;
}

// --------------------------------- init ------------------------------------
__global__ void init_kernel() {
    int i = blockIdx.x * blockDim.x + threadIdx.x;
    if (i < NH * NB) ((float*)g_hy)[i] = 0.0f;  // buffer 0 only (step 0 reads it)
    if (i < 64) g_bar2[i] = 0u;
}

// --------------- xw[t][b][n] = sum_i x[b][t][i] * x2h[i][n] ----------------
__global__ void xw_kernel(const float* __restrict__ x,
                          const float* __restrict__ x2h) {
    __shared__ float xS[64][64];
    const int t = blockIdx.y, n0 = blockIdx.x * 128, tid = threadIdx.x;
    {
        int b = tid >> 2, part = tid & 3;
        const float4* src = (const float4*)(x + ((size_t)b * TT + t) * 64 + part * 16);
        float4* dst = (float4*)&xS[b][part * 16];
        dst[0] = src[0]; dst[1] = src[1]; dst[2] = src[2]; dst[3] = src[3];
    }
    __syncthreads();
    const int n = n0 + (tid & 127);
    const int b0 = (tid >> 7) * 32;
    float acc[32];
#pragma unroll
    for (int bb = 0; bb < 32; ++bb) acc[bb] = 0.0f;
    for (int i = 0; i < 64; ++i) {
        float w = __ldg(&x2h[(size_t)i * NH + n]);
#pragma unroll
        for (int bb = 0; bb < 32; ++bb) acc[bb] = fmaf(xS[b0 + bb][i], w, acc[bb]);
    }
#pragma unroll
    for (int bb = 0; bb < 32; ++bb)
        g_xw[((size_t)t * NB + b0 + bb) * NH + n] = acc[bb];
}

// ----------------- persistent harmonic kernel (256 steps + hyW) ------------
// 128 CTAs = 64 col-blocks x 2 batch-halves (independent barrier per half).
// CTA owns 16 cols x 32 batches. GEMM: lane b = b0+(tid&31), K-split tid>>5.
// Update: j = tid&15, ub = tid>>4 -> states (j,ub),(j,ub+16) in registers.
__global__ void __launch_bounds__(256, 1) harm_kernel(
    const float* __restrict__ W, const float* __restrict__ bias,
    const float* __restrict__ gam, const float* __restrict__ eps,
    float* __restrict__ out) {
    extern __shared__ float sm[];
    float* Wb = sm;                  // [1024][16]   64 KB
    float* P  = sm + NH * 16;        // [8][16][33]  16.9 KB

    const int tid = threadIdx.x;
    const int n0 = (blockIdx.x >> 1) * 16, b0 = (blockIdx.x & 1) * 32;
    unsigned* barp = &g_bar2[(blockIdx.x & 1) * 32];

    // load W slice ONCE for the whole run
    for (int k = tid; k < NH; k += 256) {
        const float4* src = (const float4*)(W + (size_t)k * NH + n0);
        float4* dst = (float4*)(Wb + k * 16);
        dst[0] = src[0]; dst[1] = src[1]; dst[2] = src[2]; dst[3] = src[3];
    }

    const int uj = tid & 15, ub = tid >> 4;
    const int n_u = n0 + uj;
    const float bi = bias[n_u], ga = gam[n_u], ep = eps[n_u];
    float hyA = 0.0f, hzA = 0.0f, hyB = 0.0f, hzB = 0.0f;

    const int bg = b0 + (tid & 31), kp = tid >> 5, k0 = kp * 128;
    const int bl = tid & 31;

    // prefetch xw for step 0
    float xwA = __ldg(&g_xw[((size_t)(b0 + ub)) * NH + n_u]);
    float xwB = __ldg(&g_xw[((size_t)(b0 + ub + 16)) * NH + n_u]);
    __syncthreads();

    for (int s = 0; s <= THH; ++s) {
        const int cur = s & 1;
        const float* hyp = &g_hy[cur][0][0];

        // ---- GEMM: acc over this thread's 128-k slice, 16 cols as 8 f32x2 ----
        ull acc[8];
#pragma unroll
        for (int p = 0; p < 8; ++p) acc[p] = 0ull;
        float hb[8];
#pragma unroll
        for (int q = 0; q < 8; ++q) hb[q] = __ldcg(hyp + (size_t)(k0 + q) * NB + bg);
        for (int kb = 0; kb < 128; kb += 8) {
            float hc[8];
#pragma unroll
            for (int q = 0; q < 8; ++q) hc[q] = hb[q];
            if (kb + 8 < 128) {
#pragma unroll
                for (int q = 0; q < 8; ++q)
                    hb[q] = __ldcg(hyp + (size_t)(k0 + kb + 8 + q) * NB + bg);
            }
#pragma unroll
            for (int q = 0; q < 8; ++q) {
                ull hh = pack2(hc[q]);
                const ulonglong2* wp = (const ulonglong2*)(Wb + (k0 + kb + q) * 16);
                ulonglong2 A = wp[0], B2 = wp[1], C = wp[2], D = wp[3];
                acc[0] = fma2(hh, A.x, acc[0]);  acc[1] = fma2(hh, A.y, acc[1]);
                acc[2] = fma2(hh, B2.x, acc[2]); acc[3] = fma2(hh, B2.y, acc[3]);
                acc[4] = fma2(hh, C.x, acc[4]);  acc[5] = fma2(hh, C.y, acc[5]);
                acc[6] = fma2(hh, D.x, acc[6]);  acc[7] = fma2(hh, D.y, acc[7]);
            }
        }
        // partials -> SMEM (lanes vary b: conflict-free)
        {
            float* pr = P + (size_t)kp * 16 * 33;
#pragma unroll
            for (int p = 0; p < 8; ++p) {
                float lo, hi; unpack2(acc[p], lo, hi);
                pr[(2 * p) * 33 + bl] = lo;
                pr[(2 * p + 1) * 33 + bl] = hi;
            }
        }
        __syncthreads();

        // ---- reduce over 8 K-splits ----
        float sA = 0.0f, sB = 0.0f;
#pragma unroll
        for (int q = 0; q < 8; ++q) {
            const float* pr = P + ((size_t)q * 16 + uj) * 33;
            sA += pr[ub];
            sB += pr[ub + 16];
        }

        if (s < THH) {
            // ---- fused update (2 states per thread, register-resident) ----
            float tA = tanhf(sA + xwA + bi);
            hzA = hzA + 0.042f * (tA - ga * hyA - ep * hzA);
            hyA = hyA + 0.042f * hzA;
            float tB = tanhf(sB + xwB + bi);
            hzB = hzB + 0.042f * (tB - ga * hyB - ep * hzB);
            hyB = hyB + 0.042f * hzB;

            g_hy[cur ^ 1][n_u][b0 + ub]      = hyA;
            g_hy[cur ^ 1][n_u][b0 + ub + 16] = hyB;
            if (s == THH - 1) {
                g_hz[n_u][b0 + ub]      = hzA;
                g_hz[n_u][b0 + ub + 16] = hzB;
            }
            __syncthreads();                    // all hy writes issued
            if (tid == 0) bar_arrive(barp);     // release: orders CTA's hy writes

            // overlap with barrier wait: trajectory stores + next xw prefetch
            size_t oA = ((size_t)(b0 + ub) * TT + s) * NH + n_u;
            size_t oB = ((size_t)(b0 + ub + 16) * TT + s) * NH + n_u;
            out[oA] = hyA;             out[oB] = hyB;
            out[HZS_OFF + oA] = hzA;   out[HZS_OFF + oB] = hzB;
            if (s + 1 < THH) {
                xwA = __ldg(&g_xw[((size_t)(s + 1) * NB + b0 + ub) * NH + n_u]);
                xwB = __ldg(&g_xw[((size_t)(s + 1) * NB + b0 + ub + 16) * NH + n_u]);
            }

            if (tid == 0) {
                const unsigned tgt = 64u * (unsigned)(s + 1);
                while (bar_peek(barp) < tgt) { }
            }
            __syncthreads();
        } else {
            // s == 256: hyW = hy_final @ h2h
            g_hyW[(size_t)(b0 + ub) * NH + n_u]      = sA;
            g_hyW[(size_t)(b0 + ub + 16) * NH + n_u] = sB;
        }
    }
}

// ------------------------- spiking (LIF) phase -----------------------------
__global__ void spike_kernel(float* __restrict__ out) {
    const int idx = blockIdx.x * 256 + threadIdx.x;   // 65536 threads
    const int b = idx >> 10, n = idx & 1023;
    const float hw = g_hyW[idx];
    const float* xp = g_xw + (size_t)b * NH + n;
    float* us = out + US_OFF + (size_t)b * THH * NH + n;
    float* sp = out + SP_OFF + (size_t)b * THH * NH + n;
    float u = 0.0f;
#pragma unroll 4
    for (int t = 0; t < THH; ++t) {
        float xv = __ldg(xp + (size_t)t * (NB * NH));
        float spike = (u > 0.008f) ? 1.0f : 0.0f;
        u = (u > 0.008f) ? 0.001f : u;
        u = u + (-u + hw + xv) * 0.00105f;
        us[(size_t)t * NH] = u;
        sp[(size_t)t * NH] = spike;
    }
}

// ----------- broadcast hy/hz into trajectory for t in [256, 512) -----------
__global__ void fill_kernel(float* __restrict__ out) {
    const int idx = blockIdx.x * blockDim.x + threadIdx.x;  // 16384 threads
    const int b = idx >> 8, n4 = (idx & 255) * 4;
    float4 hy = make_float4(g_hy[0][n4][b], g_hy[0][n4 + 1][b],
                            g_hy[0][n4 + 2][b], g_hy[0][n4 + 3][b]);
    float4 hz = make_float4(g_hz[n4][b], g_hz[n4 + 1][b],
                            g_hz[n4 + 2][b], g_hz[n4 + 3][b]);
    float* hys = out + ((size_t)b * TT + THH) * NH + n4;
    float* hzs = out + HZS_OFF + ((size_t)b * TT + THH) * NH + n4;
#pragma unroll 4
    for (int t = 0; t < THH; ++t) {
        *(float4*)(hys + (size_t)t * NH) = hy;
        *(float4*)(hzs + (size_t)t * NH) = hz;
    }
}

// ---------------------------------------------------------------------------
extern "C" void kernel_launch(void* const* d_in, const int* in_sizes, int n_in,
                              void* d_out, int out_size) {
    const float* x    = (const float*)d_in[0];
    const float* x2h  = (const float*)d_in[1];
    const float* h2h  = (const float*)d_in[2];
    const float* bias = (const float*)d_in[3];
    const float* gam  = (const float*)d_in[4];
    const float* eps  = (const float*)d_in[5];
    float* out = (float*)d_out;

    const int smem = NH * 16 * 4 + 8 * 16 * 33 * 4;   // 82432 B
    static int attr_done = 0;
    if (!attr_done) {
        cudaFuncSetAttribute(harm_kernel,
                             cudaFuncAttributeMaxDynamicSharedMemorySize, smem);
        attr_done = 1;
    }

    init_kernel<<<256, 256>>>();
    xw_kernel<<<dim3(8, 256), 256>>>(x, x2h);
    harm_kernel<<<NCTA, 256, smem>>>(h2h, bias, gam, eps, out);
    spike_kernel<<<256, 256>>>(out);
    fill_kernel<<<64, 256>>>(out);
}

// round 13
// speedup vs baseline: 3.3470x; 1.3422x over previous
#include <cuda_runtime.h>

#define NH 1024
#define NB 64
#define TT 512
#define THH 256
#define NCTA 128

// output layout (floats): hys[B,T,H] | hzs[B,T,H] | us[B,256,H] | spikes[B,256,H]
#define HZS_OFF 33554432ull
#define US_OFF  67108864ull
#define SP_OFF  83886080ull

typedef unsigned long long ull;

// ---------------- device scratch (static globals: allocation-free) ---------
__device__ float g_hy[2][NH][NB];              // ping-pong hy, transposed [k][b]
__device__ float g_hz[NH][NB];                 // final hz, transposed
__device__ float g_xw[(size_t)THH * NB * NH];  // x_t @ x2h, [t][b][n]
__device__ float g_hyW[NB * NH];               // hy_final @ h2h, [b][n]
__device__ unsigned g_bar2[64];                // [0] and [32]: per-half counters

__device__ __forceinline__ ull fma2(ull a, ull b, ull c) {
    ull d; asm("fma.rn.f32x2 %0, %1, %2, %3;" : "=l"(d) : "l"(a), "l"(b), "l"(c));
    return d;
}
__device__ __forceinline__ ull pack2(float x) {
    ull r; asm("mov.b64 %0, {%1, %1};" : "=l"(r) : "f"(x)); return r;
}
__device__ __forceinline__ void unpack2(ull v, float& lo, float& hi) {
    asm("mov.b64 {%0, %1}, %2;" : "=f"(lo), "=f"(hi) : "l"(v));
}
__device__ __forceinline__ void bar_arrive(unsigned* p) {
    asm volatile("red.release.gpu.global.add.u32 [%0], 1;" :: "l"(p) : "memory");
}
__device__ __forceinline__ unsigned bar_peek(unsigned* p) {
    unsigned v;
    asm volatile("ld.acquire.gpu.global.u32 %0, [%1];" : "=r"(v) : "l"(p) : "memory");
    return v;
}

// --------------------------------- init ------------------------------------
__global__ void init_kernel() {
    int i = blockIdx.x * blockDim.x + threadIdx.x;
    if (i < NH * NB) ((float*)g_hy)[i] = 0.0f;  // buffer 0 only (step 0 reads it)
    if (i < 64) g_bar2[i] = 0u;
}

// --------------- xw[t][b][n] = sum_i x[b][t][i] * x2h[i][n] ----------------
__global__ void xw_kernel(const float* __restrict__ x,
                          const float* __restrict__ x2h) {
    __shared__ float xS[64][64];
    const int t = blockIdx.y, n0 = blockIdx.x * 128, tid = threadIdx.x;
    {
        int b = tid >> 2, part = tid & 3;
        const float4* src = (const float4*)(x + ((size_t)b * TT + t) * 64 + part * 16);
        float4* dst = (float4*)&xS[b][part * 16];
        dst[0] = src[0]; dst[1] = src[1]; dst[2] = src[2]; dst[3] = src[3];
    }
    __syncthreads();
    const int n = n0 + (tid & 127);
    const int b0 = (tid >> 7) * 32;
    float acc[32];
#pragma unroll
    for (int bb = 0; bb < 32; ++bb) acc[bb] = 0.0f;
    for (int i = 0; i < 64; ++i) {
        float w = __ldg(&x2h[(size_t)i * NH + n]);
#pragma unroll
        for (int bb = 0; bb < 32; ++bb) acc[bb] = fmaf(xS[b0 + bb][i], w, acc[bb]);
    }
#pragma unroll
    for (int bb = 0; bb < 32; ++bb)
        g_xw[((size_t)t * NB + b0 + bb) * NH + n] = acc[bb];
}

// ----------------- persistent harmonic kernel (256 steps + hyW) ------------
// 128 CTAs = 64 col-blocks x 2 batch-halves (independent barrier per half).
// CTA owns 16 cols x 32 batches, K = 1024.
// GEMM role: thread tile = 4 b x 8 cols x 64 k.
//   bq = tid&7 (b-quad), cg = (tid>>3)&1 (col half), kp = tid>>4 (k-split 16).
// Update role: uj = tid&15 (col), ub = tid>>4 -> states (uj, ub), (uj, ub+16)
//   register-resident across all steps.
__global__ void __launch_bounds__(256, 1) harm_kernel(
    const float* __restrict__ W, const float* __restrict__ bias,
    const float* __restrict__ gam, const float* __restrict__ eps,
    float* __restrict__ out) {
    extern __shared__ float sm[];
    float* Wb = sm;                  // [1024][16]        64 KB
    float* P  = sm + NH * 16;        // [16*16][33]       33 KB

    const int tid = threadIdx.x;
    const int n0 = (blockIdx.x >> 1) * 16, b0 = (blockIdx.x & 1) * 32;
    unsigned* barp = &g_bar2[(blockIdx.x & 1) * 32];

    // load W slice ONCE for the whole run
    for (int k = tid; k < NH; k += 256) {
        const float4* src = (const float4*)(W + (size_t)k * NH + n0);
        float4* dst = (float4*)(Wb + k * 16);
        dst[0] = src[0]; dst[1] = src[1]; dst[2] = src[2]; dst[3] = src[3];
    }

    // update-role constants/state
    const int uj = tid & 15, ub = tid >> 4;
    const int n_u = n0 + uj;
    const float bi = bias[n_u], ga = gam[n_u], ep = eps[n_u];
    float hyA = 0.0f, hzA = 0.0f, hyB = 0.0f, hzB = 0.0f;

    // GEMM-role constants
    const int bq = tid & 7;              // b-quad: local b = bq*4 .. +3
    const int cg = (tid >> 3) & 1;       // col half
    const int kp = tid >> 4;             // 0..15
    const int c0 = cg * 8;
    const int k0 = kp * 64;
    const int bb = b0 + bq * 4;          // global batch base (16B-aligned)

    // prefetch xw for step 0
    float xwA = __ldg(&g_xw[((size_t)(b0 + ub)) * NH + n_u]);
    float xwB = __ldg(&g_xw[((size_t)(b0 + ub + 16)) * NH + n_u]);
    __syncthreads();

    for (int s = 0; s <= THH; ++s) {
        const int cur = s & 1;
        const float* hyk = &g_hy[cur][0][0] + (size_t)k0 * NB + bb;

        // ---- GEMM: 4 b x 8 cols x 64 k, acc as 16 f32x2 (col-pairs) ----
        ull acc[16];
#pragma unroll
        for (int p = 0; p < 16; ++p) acc[p] = 0ull;

        float4 hb[4];
#pragma unroll
        for (int q = 0; q < 4; ++q)
            hb[q] = __ldcg((const float4*)(hyk + (size_t)q * NB));

        for (int kb = 0; kb < 64; kb += 4) {
            float4 hc[4];
#pragma unroll
            for (int q = 0; q < 4; ++q) hc[q] = hb[q];
            if (kb + 4 < 64) {
#pragma unroll
                for (int q = 0; q < 4; ++q)
                    hb[q] = __ldcg((const float4*)(hyk + (size_t)(kb + 4 + q) * NB));
            }
#pragma unroll
            for (int q = 0; q < 4; ++q) {
                const float* wrow = Wb + (k0 + kb + q) * 16 + c0;
                ulonglong2 wA = *(const ulonglong2*)(wrow);
                ulonglong2 wB = *(const ulonglong2*)(wrow + 4);
                ull hh;
                hh = pack2(hc[q].x);
                acc[0]  = fma2(hh, wA.x, acc[0]);  acc[1]  = fma2(hh, wA.y, acc[1]);
                acc[2]  = fma2(hh, wB.x, acc[2]);  acc[3]  = fma2(hh, wB.y, acc[3]);
                hh = pack2(hc[q].y);
                acc[4]  = fma2(hh, wA.x, acc[4]);  acc[5]  = fma2(hh, wA.y, acc[5]);
                acc[6]  = fma2(hh, wB.x, acc[6]);  acc[7]  = fma2(hh, wB.y, acc[7]);
                hh = pack2(hc[q].z);
                acc[8]  = fma2(hh, wA.x, acc[8]);  acc[9]  = fma2(hh, wA.y, acc[9]);
                acc[10] = fma2(hh, wB.x, acc[10]); acc[11] = fma2(hh, wB.y, acc[11]);
                hh = pack2(hc[q].w);
                acc[12] = fma2(hh, wA.x, acc[12]); acc[13] = fma2(hh, wA.y, acc[13]);
                acc[14] = fma2(hh, wB.x, acc[14]); acc[15] = fma2(hh, wB.y, acc[15]);
            }
        }

        // partials -> SMEM: P[(kp*16 + col)*33 + local_b]
        {
            const int blo = bq * 4;
#pragma unroll
            for (int bi = 0; bi < 4; ++bi) {
#pragma unroll
                for (int cp = 0; cp < 4; ++cp) {
                    float lo, hi; unpack2(acc[bi * 4 + cp], lo, hi);
                    P[(kp * 16 + c0 + 2 * cp) * 33 + blo + bi] = lo;
                    P[(kp * 16 + c0 + 2 * cp + 1) * 33 + blo + bi] = hi;
                }
            }
        }
        __syncthreads();

        // ---- reduce over 16 K-splits ----
        float sA = 0.0f, sB = 0.0f;
#pragma unroll
        for (int q = 0; q < 16; ++q) {
            const float* pr = P + (q * 16 + uj) * 33;
            sA += pr[ub];
            sB += pr[ub + 16];
        }

        if (s < THH) {
            // ---- fused update (2 states per thread, register-resident) ----
            float tA = tanhf(sA + xwA + bi);
            hzA = hzA + 0.042f * (tA - ga * hyA - ep * hzA);
            hyA = hyA + 0.042f * hzA;
            float tB = tanhf(sB + xwB + bi);
            hzB = hzB + 0.042f * (tB - ga * hyB - ep * hzB);
            hyB = hyB + 0.042f * hzB;

            g_hy[cur ^ 1][n_u][b0 + ub]      = hyA;
            g_hy[cur ^ 1][n_u][b0 + ub + 16] = hyB;
            if (s == THH - 1) {
                g_hz[n_u][b0 + ub]      = hzA;
                g_hz[n_u][b0 + ub + 16] = hzB;
            }
            __syncthreads();                    // all hy writes issued
            if (tid == 0) bar_arrive(barp);     // release: orders CTA's hy writes

            // overlap with barrier wait: trajectory stores + next xw prefetch
            size_t oA = ((size_t)(b0 + ub) * TT + s) * NH + n_u;
            size_t oB = ((size_t)(b0 + ub + 16) * TT + s) * NH + n_u;
            out[oA] = hyA;             out[oB] = hyB;
            out[HZS_OFF + oA] = hzA;   out[HZS_OFF + oB] = hzB;
            if (s + 1 < THH) {
                xwA = __ldg(&g_xw[((size_t)(s + 1) * NB + b0 + ub) * NH + n_u]);
                xwB = __ldg(&g_xw[((size_t)(s + 1) * NB + b0 + ub + 16) * NH + n_u]);
            }

            if (tid == 0) {
                const unsigned tgt = 64u * (unsigned)(s + 1);
                while (bar_peek(barp) < tgt) { }
            }
            __syncthreads();
        } else {
            // s == 256: hyW = hy_final @ h2h
            g_hyW[(size_t)(b0 + ub) * NH + n_u]      = sA;
            g_hyW[(size_t)(b0 + ub + 16) * NH + n_u] = sB;
        }
    }
}

// ------------------------- spiking (LIF) phase -----------------------------
// serial chain per (b,n); xw loads are u-independent -> batch-prefetch 8.
__global__ void spike_kernel(float* __restrict__ out) {
    const int idx = blockIdx.x * 256 + threadIdx.x;   // 65536 threads
    const int b = idx >> 10, n = idx & 1023;
    const float hw = g_hyW[idx];
    const float* xp = g_xw + (size_t)b * NH + n;
    float* us = out + US_OFF + (size_t)b * THH * NH + n;
    float* sp = out + SP_OFF + (size_t)b * THH * NH + n;
    float u = 0.0f;
    for (int tb = 0; tb < THH; tb += 8) {
        float xv[8];
#pragma unroll
        for (int i = 0; i < 8; ++i)
            xv[i] = __ldg(xp + (size_t)(tb + i) * (NB * NH));
#pragma unroll
        for (int i = 0; i < 8; ++i) {
            const int t = tb + i;
            float spike = (u > 0.008f) ? 1.0f : 0.0f;
            u = (u > 0.008f) ? 0.001f : u;
            u = u + (-u + hw + xv[i]) * 0.00105f;
            __stcs(us + (size_t)t * NH, u);
            __stcs(sp + (size_t)t * NH, spike);
        }
    }
}

// ----------- broadcast hy/hz into trajectory for t in [256, 512) -----------
// 262144 threads; each writes 16 timesteps of one float4.
__global__ void fill_kernel(float* __restrict__ out) {
    const int idx = blockIdx.x * 256 + threadIdx.x;
    const int n4 = (idx & 255) * 4;
    const int b = (idx >> 8) & 63;
    const int tc = idx >> 14;                 // 0..15
    float4 hy = make_float4(g_hy[0][n4][b], g_hy[0][n4 + 1][b],
                            g_hy[0][n4 + 2][b], g_hy[0][n4 + 3][b]);
    float4 hz = make_float4(g_hz[n4][b], g_hz[n4 + 1][b],
                            g_hz[n4 + 2][b], g_hz[n4 + 3][b]);
    const int t0 = THH + tc * 16;
    float* hys = out + ((size_t)b * TT + t0) * NH + n4;
    float* hzs = out + HZS_OFF + ((size_t)b * TT + t0) * NH + n4;
#pragma unroll
    for (int t = 0; t < 16; ++t) {
        __stcs((float4*)(hys + (size_t)t * NH), hy);
        __stcs((float4*)(hzs + (size_t)t * NH), hz);
    }
}

// ---------------------------------------------------------------------------
extern "C" void kernel_launch(void* const* d_in, const int* in_sizes, int n_in,
                              void* d_out, int out_size) {
    const float* x    = (const float*)d_in[0];
    const float* x2h  = (const float*)d_in[1];
    const float* h2h  = (const float*)d_in[2];
    const float* bias = (const float*)d_in[3];
    const float* gam  = (const float*)d_in[4];
    const float* eps  = (const float*)d_in[5];
    float* out = (float*)d_out;

    const int smem = NH * 16 * 4 + 16 * 16 * 33 * 4;   // 99328 B
    static int attr_done = 0;
    if (!attr_done) {
        cudaFuncSetAttribute(harm_kernel,
                             cudaFuncAttributeMaxDynamicSharedMemorySize, smem);
        attr_done = 1;
    }

    init_kernel<<<256, 256>>>();
    xw_kernel<<<dim3(8, 256), 256>>>(x, x2h);
    harm_kernel<<<NCTA, 256, smem>>>(h2h, bias, gam, eps, out);
    spike_kernel<<<256, 256>>>(out);
    fill_kernel<<<1024, 256>>>(out);
}